// round 10
// baseline (speedup 1.0000x reference)
#include <cuda_runtime.h>
#include <cstdint>

#define B_ 8
#define S_ 4096
#define D_ 1024
#define L_ 16

#define TR   16             // tile rows
#define NT   16             // tiles per CTA -> 256 rows
#define CTAB 16
#define GRID (B_*CTAB)      // 128
#define THR  512            // warps 0-7 scores, 8-15 ctx
#define TP   1028           // tile pitch (conflict-free scores-B)
#define EP   20             // e-1 pitch (conflict-free ctx-A)
#define RP   18
#define BUF  (TR*TP)        // 16448 floats

#define OFF_RD (3*BUF)                 // 49344
#define RDP    (8*L_*RP)               // 2304 per parity
#define OFF_ES (OFF_RD + 2*RDP)        // 53952
#define ESP    (L_*EP)                 // 320
#define OFF_ZB (OFF_ES + 2*ESP)        // 54592
#define SMEM_FLOATS (OFF_ZB + L_*RP)   // 54880
#define SMEM_BYTES  (SMEM_FLOATS*4)    // 219,520 B

__device__ float g_G[(size_t)GRID*L_*D_];   // per-CTA ctx partials (8 MB)
__device__ float g_cs[GRID*D_];             // per-CTA column sums
__device__ float g_z[GRID*L_];              // per-CTA sum(e-1)

__device__ __forceinline__ void cpa16(uint32_t saddr, const void* gaddr) {
    asm volatile("cp.async.ca.shared.global [%0], [%1], 16;\n" :: "r"(saddr), "l"(gaddr));
}
__device__ __forceinline__ void mma_tf32(float* c, const float* a, const float* b) {
    asm volatile(
        "mma.sync.aligned.m16n8k8.row.col.f32.tf32.tf32.f32 "
        "{%0,%1,%2,%3}, {%4,%5,%6,%7}, {%8,%9}, {%0,%1,%2,%3};\n"
        : "+f"(c[0]), "+f"(c[1]), "+f"(c[2]), "+f"(c[3])
        : "f"(a[0]), "f"(a[1]), "f"(a[2]), "f"(a[3]), "f"(b[0]), "f"(b[1]));
}

// ---------------------------------------------------------------------------
// Fused, software-pipelined, warp-specialized:
//   interval P2: warps0-7 scores(i)  ||  warps8-15 ctx(i-1)
//   interval P3: warps0-7 exp(i)     ||  warps8-15 colsum(i)   + stage(i+2)
// memory read exactly once; triple-buffered tiles; summ in registers.
// ---------------------------------------------------------------------------
__global__ void __launch_bounds__(THR, 1)
kMain(const float* __restrict__ mem, const float* __restrict__ summ) {
    extern __shared__ float sA[];
    const int t    = threadIdx.x;
    const int bx   = blockIdx.x;
    const int warp = t >> 5;
    const int lane = t & 31;
    const int g    = lane >> 2;
    const int tig  = lane & 3;
    const uint32_t sbase = (uint32_t)__cvta_generic_to_shared(sA);

    const int b    = bx >> 4;
    const int row0 = (bx & 15) * (TR*NT);
    const float* gbase = mem + ((size_t)b*S_ + row0)*D_;

    const int sr = t >> 5;            // staging row = warp id (0..15)
    const int sc = (t & 31) * 4;

#define STAGE(i) do {                                                          \
        const float* gp = gbase + ((size_t)((i)*TR + sr))*D_ + sc;             \
        uint32_t sp = sbase + 4u*(((i)%3)*BUF + sr*TP + sc);                   \
        _Pragma("unroll")                                                      \
        for (int k = 0; k < 8; ++k) cpa16(sp + 4u*128*k, gp + 128*k);          \
    } while (0)
#define COMMIT() asm volatile("cp.async.commit_group;\n" ::: "memory")
#define WAIT1()  asm volatile("cp.async.wait_group 1;\n" ::: "memory")

    // ---- role-specific persistent registers ----
    float asum[16][4];                // scores warps: summ frags (k-slice 128 wide)
    float gacc[16][4];                // ctx warps: G accumulators (d-slice 128 wide)
    float colacc[4] = {0.f,0.f,0.f,0.f};
    float zacc = 0.f;
    const int lo = t >> 4, jo = t & 15;

    if (warp < 8) {
        const int k0w = warp*128;
#pragma unroll
        for (int ks = 0; ks < 16; ++ks) {
            const int k = k0w + ks*8 + tig;
            asum[ks][0] = summ[g*D_ + k];
            asum[ks][1] = summ[(g+8)*D_ + k];
            asum[ks][2] = summ[g*D_ + k + 4];
            asum[ks][3] = summ[(g+8)*D_ + k + 4];
        }
    } else {
#pragma unroll
        for (int nt = 0; nt < 16; ++nt) { gacc[nt][0]=0.f; gacc[nt][1]=0.f; gacc[nt][2]=0.f; gacc[nt][3]=0.f; }
    }

    STAGE(0); COMMIT();
    STAGE(1); COMMIT();

    for (int it = 0; it < NT; ++it) {
        const int p  = it & 1;
        const float* tile = sA + (it % 3)*BUF;

        WAIT1();
        __syncthreads();                       // A: staging visible; prev P3 done

        if (warp < 8) {
            // ---- scores(it): k-slice [128*warp, +128) ----
            float s0[4] = {0.f,0.f,0.f,0.f}, s1[4] = {0.f,0.f,0.f,0.f};
            const int k0w = warp*128;
#pragma unroll
            for (int ks = 0; ks < 16; ++ks) {
                const int k0 = k0w + ks*8;
                float b0[2], b1[2];
                b0[0] = tile[g*TP     + k0 + tig];
                b0[1] = tile[g*TP     + k0 + tig + 4];
                b1[0] = tile[(8+g)*TP + k0 + tig];
                b1[1] = tile[(8+g)*TP + k0 + tig + 4];
                mma_tf32(s0, asum[ks], b0);
                mma_tf32(s1, asum[ks], b1);
            }
            float* red = sA + OFF_RD + p*RDP + warp*(L_*RP);
            *(float2*)&red[g*RP     + 2*tig]     = make_float2(s0[0], s0[1]);
            *(float2*)&red[(g+8)*RP + 2*tig]     = make_float2(s0[2], s0[3]);
            *(float2*)&red[g*RP     + 8 + 2*tig] = make_float2(s1[0], s1[1]);
            *(float2*)&red[(g+8)*RP + 8 + 2*tig] = make_float2(s1[2], s1[3]);
        } else if (it > 0) {
            // ---- ctx(it-1): d-slice [(warp-8)*128, +128) ----
            const float* tprev = sA + ((it-1) % 3)*BUF;
            const float* es = sA + OFF_ES + ((it-1) & 1)*ESP;
            const int n0w = (warp-8)*128;
#pragma unroll
            for (int ksx = 0; ksx < 2; ++ksx) {
                const int k0 = ksx*8;
                float a[4];
                a[0] = es[g*EP     + k0 + tig];
                a[1] = es[(g+8)*EP + k0 + tig];
                a[2] = es[g*EP     + k0 + tig + 4];
                a[3] = es[(g+8)*EP + k0 + tig + 4];
#pragma unroll
                for (int nt = 0; nt < 16; ++nt) {
                    const int n0 = n0w + nt*8;
                    float bfr[2];
                    bfr[0] = tprev[(k0+tig)*TP   + n0 + g];
                    bfr[1] = tprev[(k0+tig+4)*TP + n0 + g];
                    mma_tf32(gacc[nt], a, bfr);
                }
            }
        }
        __syncthreads();                       // B: red ready; buf(it-1) free

        if (it + 2 < NT) STAGE(it + 2);
        COMMIT();                              // always commit (keeps group count)

        if (t < 256) {
            // ---- exp(it): cross-warp reduce over 8 k-slices ----
            const float* red = sA + OFF_RD + p*RDP;
            float scv = 0.f;
#pragma unroll
            for (int w = 0; w < 8; ++w) scv += red[w*(L_*RP) + lo*RP + jo];
            float em1 = __expf(scv * 0.03125f) - 1.0f;   // scores O(0.05): no max sub
            sA[OFF_ES + p*ESP + lo*EP + jo] = em1;
            zacc += em1;
        } else {
            // ---- colsum(it): exact fp32, 4 cols/thread ----
            const int t2 = t - 256;
#pragma unroll
            for (int r = 0; r < TR; ++r) {
                float4 v = *(const float4*)&tile[r*TP + 4*t2];
                colacc[0] += v.x; colacc[1] += v.y; colacc[2] += v.z; colacc[3] += v.w;
            }
        }
    }
#undef STAGE

    __syncthreads();
    // ---- drain: ctx(NT-1) ----
    if (warp >= 8) {
        const float* tprev = sA + ((NT-1) % 3)*BUF;
        const float* es = sA + OFF_ES + ((NT-1) & 1)*ESP;
        const int n0w = (warp-8)*128;
#pragma unroll
        for (int ksx = 0; ksx < 2; ++ksx) {
            const int k0 = ksx*8;
            float a[4];
            a[0] = es[g*EP     + k0 + tig];
            a[1] = es[(g+8)*EP + k0 + tig];
            a[2] = es[g*EP     + k0 + tig + 4];
            a[3] = es[(g+8)*EP + k0 + tig + 4];
#pragma unroll
            for (int nt = 0; nt < 16; ++nt) {
                const int n0 = n0w + nt*8;
                float bfr[2];
                bfr[0] = tprev[(k0+tig)*TP   + n0 + g];
                bfr[1] = tprev[(k0+tig+4)*TP + n0 + g];
                mma_tf32(gacc[nt], a, bfr);
            }
        }
        // write G partials + column sums
        const int t2 = t - 256;
        *(float4*)&g_cs[bx*D_ + 4*t2] = make_float4(colacc[0], colacc[1], colacc[2], colacc[3]);
#pragma unroll
        for (int nt = 0; nt < 16; ++nt) {
            const int d0 = n0w + nt*8 + 2*tig;
            *(float2*)&g_G[((size_t)bx*L_ + g    )*D_ + d0] = make_float2(gacc[nt][0], gacc[nt][1]);
            *(float2*)&g_G[((size_t)bx*L_ + g + 8)*D_ + d0] = make_float2(gacc[nt][2], gacc[nt][3]);
        }
    } else {
        sA[OFF_ZB + lo*RP + jo] = zacc;        // t < 256
    }
    __syncthreads();
    if (t < L_) {
        float z = 0.f;
#pragma unroll
        for (int j = 0; j < 16; ++j) z += sA[OFF_ZB + t*RP + j];
        g_z[bx*L_ + t] = z;                    // sum(e-1); +S added in kF
    }
}

// ---------------------------------------------------------------------------
// Reduce: out[b,d] = C0*colsum + sum_l c_bl*G.  512 blocks (8 b x 64 d-chunks
// of 16), 256 thr = 16 j-groups x 16 d-lanes.
// ---------------------------------------------------------------------------
__global__ void __launch_bounds__(256, 2)
kF(const float* __restrict__ wproj, float* __restrict__ out) {
    const int t  = threadIdx.x;
    const int bx = blockIdx.x;
    const int b  = bx >> 6;
    const int dc = bx & 63;
    const int dd = t & 15;
    const int jg = t >> 4;                // 0..15 = which source CTA
    const int d  = dc*16 + dd;

    __shared__ float cl[L_];
    __shared__ float C0s;
    __shared__ float sred[16][17];

    if (t < L_) {
        float Z = (float)S_;
#pragma unroll
        for (int j = 0; j < CTAB; ++j) Z += g_z[(b*CTAB + j)*L_ + t];
        cl[t] = wproj[t] / Z;
    }
    __syncthreads();
    if (t == 0) {
        float c0 = 0.f;
#pragma unroll
        for (int l = 0; l < L_; ++l) c0 += cl[l];
        C0s = c0;
    }
    __syncthreads();

    const int j = jg;
    float pacc = C0s * g_cs[(b*CTAB + j)*D_ + d];
    const float* Gp = &g_G[((size_t)(b*CTAB + j))*L_*D_ + d];
#pragma unroll
    for (int l = 0; l < L_; ++l) pacc += cl[l] * Gp[(size_t)l*D_];
    sred[jg][dd] = pacc;
    __syncthreads();
    if (t < 16) {
        float r = 0.f;
#pragma unroll
        for (int jj = 0; jj < 16; ++jj) r += sred[jj][t];
        out[b*D_ + dc*16 + t] = r;
    }
}

// ---------------------------------------------------------------------------
extern "C" void kernel_launch(void* const* d_in, const int* in_sizes, int n_in,
                              void* d_out, int out_size) {
    const float* mem = nullptr;
    const float* summ = nullptr;
    const float* w = nullptr;
    for (int i = 0; i < n_in; ++i) {
        if      (in_sizes[i] == B_*S_*D_) mem  = (const float*)d_in[i];
        else if (in_sizes[i] == L_*D_)    summ = (const float*)d_in[i];
        else if (in_sizes[i] == L_)       w    = (const float*)d_in[i];
    }
    static bool attrDone = false;
    if (!attrDone) {
        cudaFuncSetAttribute(kMain, cudaFuncAttributeMaxDynamicSharedMemorySize, SMEM_BYTES);
        attrDone = true;
    }
    kMain<<<GRID, THR, SMEM_BYTES>>>(mem, summ);
    kF<<<512, 256>>>(w, (float*)d_out);
}

// round 14
// speedup vs baseline: 1.4103x; 1.4103x over previous
#include <cuda_runtime.h>
#include <cstdint>

#define B_ 8
#define S_ 4096
#define D_ 1024
#define L_ 16

#define TR   16
#define NT   16
#define CTAB 16
#define GRID (B_*CTAB)      // 128
#define THR  512            // 16 warps, uniform roles
#define TP   1028           // tile pitch: conflict-free for both MMA B-reads
#define EP   20
#define RP   18
#define BUF  (TR*TP)        // 16448 floats

#define OFF_RD (2*BUF)                 // 32896  (16 warps x 16l x RP)
#define OFF_ES (OFF_RD + 16*L_*RP)     // 37504
#define OFF_ZB (OFF_ES + L_*EP)        // 37824
#define SMEM_FLOATS (OFF_ZB + L_*RP)   // 38112
#define SMEM_BYTES  (SMEM_FLOATS*4)    // 152,448 B

__device__ float g_G[(size_t)GRID*L_*D_];   // per-CTA ctx partials (8 MB)
__device__ float g_cs[GRID*D_];             // per-CTA column sums
__device__ float g_z[GRID*L_];              // per-CTA sum(e-1)

__device__ __forceinline__ void cpa16(uint32_t saddr, const void* gaddr) {
    asm volatile("cp.async.ca.shared.global [%0], [%1], 16;\n" :: "r"(saddr), "l"(gaddr));
}
__device__ __forceinline__ void mma_tf32(float* c, const float* a, const float* b) {
    asm volatile(
        "mma.sync.aligned.m16n8k8.row.col.f32.tf32.tf32.f32 "
        "{%0,%1,%2,%3}, {%4,%5,%6,%7}, {%8,%9}, {%0,%1,%2,%3};\n"
        : "+f"(c[0]), "+f"(c[1]), "+f"(c[2]), "+f"(c[3])
        : "f"(a[0]), "f"(a[1]), "f"(a[2]), "f"(a[3]), "f"(b[0]), "f"(b[1]));
}

// ---------------------------------------------------------------------------
// Fused single-read kernel. Per 16-row tile:
//  P1: scores MMA (K split 16 warps, summ frags in regs)
//  P2: exp (256 thr)
//  P3: ctx MMA (d split 16 warps) with colsum folded into B-frag registers
// ---------------------------------------------------------------------------
__global__ void __launch_bounds__(THR, 1)
kMain(const float* __restrict__ mem, const float* __restrict__ summ) {
    extern __shared__ float sA[];
    const int t    = threadIdx.x;
    const int bx   = blockIdx.x;
    const int warp = t >> 5;
    const int lane = t & 31;
    const int g    = lane >> 2;
    const int tig  = lane & 3;
    const uint32_t sbase = (uint32_t)__cvta_generic_to_shared(sA);

    const int b    = bx >> 4;
    const int row0 = (bx & 15) * (TR*NT);
    const float* gbase = mem + ((size_t)b*S_ + row0)*D_;

    const int sr = t >> 5;
    const int sc = (t & 31) * 4;

#define STAGE(i, buf) do {                                                     \
        const float* gp = gbase + ((size_t)((i)*TR + sr))*D_ + sc;             \
        uint32_t sp = sbase + 4u*((buf)*BUF + sr*TP + sc);                     \
        _Pragma("unroll")                                                      \
        for (int k = 0; k < 8; ++k) cpa16(sp + 4u*128*k, gp + 128*k);          \
        asm volatile("cp.async.commit_group;\n" ::: "memory");                 \
    } while (0)

    // summ A-frags in registers: warp k-slice [64w, 64w+64)
    float asum[8][4];
    {
        const int k0w = warp*64;
#pragma unroll
        for (int ks = 0; ks < 8; ++ks) {
            const int k = k0w + ks*8 + tig;
            asum[ks][0] = summ[g*D_ + k];
            asum[ks][1] = summ[(g+8)*D_ + k];
            asum[ks][2] = summ[g*D_ + k + 4];
            asum[ks][3] = summ[(g+8)*D_ + k + 4];
        }
    }

    float gacc[8][4];
#pragma unroll
    for (int nt = 0; nt < 8; ++nt) { gacc[nt][0]=0.f; gacc[nt][1]=0.f; gacc[nt][2]=0.f; gacc[nt][3]=0.f; }
    float colacc[8];
#pragma unroll
    for (int nt = 0; nt < 8; ++nt) colacc[nt] = 0.f;
    float zacc = 0.f;
    const int lo = t >> 4, jo = t & 15;

    STAGE(0, 0);

    for (int it = 0; it < NT; ++it) {
        if (it + 1 < NT) {
            STAGE(it + 1, (it + 1) & 1);
            asm volatile("cp.async.wait_group 1;\n" ::: "memory");
        } else {
            asm volatile("cp.async.wait_group 0;\n" ::: "memory");
        }
        __syncthreads();

        const float* tile = sA + (it & 1)*BUF;

        // ---- P1 scores: warp k-slice [64w, +64) ----
        {
            float s0[4] = {0.f,0.f,0.f,0.f}, s1[4] = {0.f,0.f,0.f,0.f};
            const int k0w = warp*64;
#pragma unroll
            for (int ks = 0; ks < 8; ++ks) {
                const int k0 = k0w + ks*8;
                float b0[2], b1[2];
                b0[0] = tile[g*TP     + k0 + tig];
                b0[1] = tile[g*TP     + k0 + tig + 4];
                b1[0] = tile[(8+g)*TP + k0 + tig];
                b1[1] = tile[(8+g)*TP + k0 + tig + 4];
                mma_tf32(s0, asum[ks], b0);
                mma_tf32(s1, asum[ks], b1);
            }
            float* red = sA + OFF_RD + warp*(L_*RP);
            *(float2*)&red[g*RP     + 2*tig]     = make_float2(s0[0], s0[1]);
            *(float2*)&red[(g+8)*RP + 2*tig]     = make_float2(s0[2], s0[3]);
            *(float2*)&red[g*RP     + 8 + 2*tig] = make_float2(s1[0], s1[1]);
            *(float2*)&red[(g+8)*RP + 8 + 2*tig] = make_float2(s1[2], s1[3]);
        }
        __syncthreads();

        // ---- P2 exp ----
        if (t < 256) {
            float scv = 0.f;
#pragma unroll
            for (int w = 0; w < 16; ++w) scv += sA[OFF_RD + w*(L_*RP) + lo*RP + jo];
            float em1 = __expf(scv * 0.03125f) - 1.0f;   // scores O(0.05): no max sub
            sA[OFF_ES + lo*EP + jo] = em1;
            zacc += em1;
        }
        __syncthreads();

        // ---- P3 ctx: warp d-slice [64w, +64); colsum folded into B-frags ----
#pragma unroll
        for (int ksx = 0; ksx < 2; ++ksx) {
            const int k0 = ksx*8;
            float a[4];
            a[0] = sA[OFF_ES + g*EP     + k0 + tig];
            a[1] = sA[OFF_ES + (g+8)*EP + k0 + tig];
            a[2] = sA[OFF_ES + g*EP     + k0 + tig + 4];
            a[3] = sA[OFF_ES + (g+8)*EP + k0 + tig + 4];
#pragma unroll
            for (int nt = 0; nt < 8; ++nt) {
                const int n0 = warp*64 + nt*8;
                float bfr[2];
                bfr[0] = tile[(k0+tig)*TP   + n0 + g];
                bfr[1] = tile[(k0+tig+4)*TP + n0 + g];
                colacc[nt] += bfr[0] + bfr[1];      // rows {tig,tig+4}+8ksx
                mma_tf32(gacc[nt], a, bfr);
            }
        }
        __syncthreads();
    }
#undef STAGE

    // ---- epilogue ----
    // colsum: reduce over tig (lanes g*4+tig share column n0+g)
#pragma unroll
    for (int nt = 0; nt < 8; ++nt) {
        float v = colacc[nt];
        v += __shfl_xor_sync(0xFFFFFFFFu, v, 1);
        v += __shfl_xor_sync(0xFFFFFFFFu, v, 2);
        if (tig == 0) g_cs[bx*D_ + warp*64 + nt*8 + g] = v;
    }

    if (t < 256) sA[OFF_ZB + lo*RP + jo] = zacc;
    __syncthreads();
    if (t < L_) {
        float z = 0.f;
#pragma unroll
        for (int j = 0; j < 16; ++j) z += sA[OFF_ZB + t*RP + j];
        g_z[bx*L_ + t] = z;                    // sum(e-1); +S added in kF
    }

#pragma unroll
    for (int nt = 0; nt < 8; ++nt) {
        const int d0 = warp*64 + nt*8 + 2*tig;
        *(float2*)&g_G[((size_t)bx*L_ + g    )*D_ + d0] = make_float2(gacc[nt][0], gacc[nt][1]);
        *(float2*)&g_G[((size_t)bx*L_ + g + 8)*D_ + d0] = make_float2(gacc[nt][2], gacc[nt][3]);
    }
}

// ---------------------------------------------------------------------------
// Reduce: out[b,d] = C0*colsum + sum_l c_bl*G
// ---------------------------------------------------------------------------
__global__ void __launch_bounds__(256, 2)
kF(const float* __restrict__ wproj, float* __restrict__ out) {
    const int t  = threadIdx.x;
    const int bx = blockIdx.x;
    const int b  = bx >> 6;
    const int dc = bx & 63;
    const int dd = t & 15;
    const int jg = t >> 4;
    const int d  = dc*16 + dd;

    __shared__ float cl[L_];
    __shared__ float C0s;
    __shared__ float sred[16][17];

    if (t < L_) {
        float Z = (float)S_;
#pragma unroll
        for (int j = 0; j < CTAB; ++j) Z += g_z[(b*CTAB + j)*L_ + t];
        cl[t] = wproj[t] / Z;
    }
    __syncthreads();
    if (t == 0) {
        float c0 = 0.f;
#pragma unroll
        for (int l = 0; l < L_; ++l) c0 += cl[l];
        C0s = c0;
    }
    __syncthreads();

    float pacc = C0s * g_cs[(b*CTAB + jg)*D_ + d];
    const float* Gp = &g_G[((size_t)(b*CTAB + jg))*L_*D_ + d];
#pragma unroll
    for (int l = 0; l < L_; ++l) pacc += cl[l] * Gp[(size_t)l*D_];
    sred[jg][dd] = pacc;
    __syncthreads();
    if (t < 16) {
        float r = 0.f;
#pragma unroll
        for (int jj = 0; jj < 16; ++jj) r += sred[jj][t];
        out[b*D_ + dc*16 + t] = r;
    }
}

// Diagnostic no-op launches: shift the ncu capture window (-s 5 -c 1) so that
// launch #6 is kMain instead of kF. Removed once kMain's profile is captured.
__global__ void kDummy() {}

// ---------------------------------------------------------------------------
extern "C" void kernel_launch(void* const* d_in, const int* in_sizes, int n_in,
                              void* d_out, int out_size) {
    const float* mem = nullptr;
    const float* summ = nullptr;
    const float* w = nullptr;
    for (int i = 0; i < n_in; ++i) {
        if      (in_sizes[i] == B_*S_*D_) mem  = (const float*)d_in[i];
        else if (in_sizes[i] == L_*D_)    summ = (const float*)d_in[i];
        else if (in_sizes[i] == L_)       w    = (const float*)d_in[i];
    }
    static bool attrDone = false;
    if (!attrDone) {
        cudaFuncSetAttribute(kMain, cudaFuncAttributeMaxDynamicSharedMemorySize, SMEM_BYTES);
        attrDone = true;
    }
    kMain<<<GRID, THR, SMEM_BYTES>>>(mem, summ);
    kF<<<512, 256>>>(w, (float*)d_out);
    kDummy<<<1, 32>>>();
    kDummy<<<1, 32>>>();
    kDummy<<<1, 32>>>();
}

// round 15
// speedup vs baseline: 1.4175x; 1.0052x over previous
#include <cuda_runtime.h>
#include <cstdint>

#define B_ 8
#define S_ 4096
#define D_ 1024
#define L_ 16

#define TR   16
#define NT   16
#define CTAB 16
#define GRID (B_*CTAB)      // 128
#define THR  512            // 16 warps
#define TP   1028           // tile pitch
#define RP   18             // score-reduce pitch (fp32)
#define EPB  12             // es bf16x2 pitch (words): 12g+tig distinct mod 32
#define BUF  (TR*TP)        // 16448 floats

#define OFF_RD (2*BUF)                 // 32896 (16 warps x 16l x RP fp32)
#define OFF_EB (OFF_RD + 16*L_*RP)     // 37504 (es bf16x2: L_ x EPB words)
#define OFF_ZB (OFF_EB + L_*EPB)       // 37696
#define SMEM_FLOATS (OFF_ZB + L_*RP)   // 37984
#define SMEM_BYTES  (SMEM_FLOATS*4)    // 151,936 B

__device__ float g_G[(size_t)GRID*L_*D_];
__device__ float g_cs[GRID*D_];
__device__ float g_z[GRID*L_];

__device__ __forceinline__ void cpa16(uint32_t saddr, const void* gaddr) {
    asm volatile("cp.async.ca.shared.global [%0], [%1], 16;\n" :: "r"(saddr), "l"(gaddr));
}
// pack two fp32 -> bf16x2 (lo in low half)
__device__ __forceinline__ uint32_t pbf(float lo, float hi) {
    uint32_t r; asm("cvt.rn.bf16x2.f32 %0, %1, %2;" : "=r"(r) : "f"(hi), "f"(lo)); return r;
}
__device__ __forceinline__ void mma_bf16(float* c, const uint32_t* a, const uint32_t* b) {
    asm volatile(
        "mma.sync.aligned.m16n8k16.row.col.f32.bf16.bf16.f32 "
        "{%0,%1,%2,%3}, {%4,%5,%6,%7}, {%8,%9}, {%0,%1,%2,%3};\n"
        : "+f"(c[0]), "+f"(c[1]), "+f"(c[2]), "+f"(c[3])
        : "r"(a[0]), "r"(a[1]), "r"(a[2]), "r"(a[3]), "r"(b[0]), "r"(b[1]));
}

// ---------------------------------------------------------------------------
// Fused single-read kernel, bf16 tensor path.
//  P1: scores MMA (k16, K split over 16 warps, summ bf16 frags in regs)
//  P2: exp + bf16x2 pack (128 threads)
//  P3: ctx MMA (k16, d split over 16 warps), colsum folded (exact fp32)
// ---------------------------------------------------------------------------
__global__ void __launch_bounds__(THR, 1)
kMain(const float* __restrict__ mem, const float* __restrict__ summ) {
    extern __shared__ float sA[];
    const int t    = threadIdx.x;
    const int bx   = blockIdx.x;
    const int warp = t >> 5;
    const int lane = t & 31;
    const int g    = lane >> 2;
    const int tig  = lane & 3;
    const uint32_t sbase = (uint32_t)__cvta_generic_to_shared(sA);

    const int b    = bx >> 4;
    const int row0 = (bx & 15) * (TR*NT);
    const float* gbase = mem + ((size_t)b*S_ + row0)*D_;

    const int sr = t >> 5;
    const int sc = (t & 31) * 4;

#define STAGE(i, buf) do {                                                     \
        const float* gp = gbase + ((size_t)((i)*TR + sr))*D_ + sc;             \
        uint32_t sp = sbase + 4u*((buf)*BUF + sr*TP + sc);                     \
        _Pragma("unroll")                                                      \
        for (int k = 0; k < 8; ++k) cpa16(sp + 4u*128*k, gp + 128*k);          \
        asm volatile("cp.async.commit_group;\n" ::: "memory");                 \
    } while (0)

    // summ bf16 A-frags: warp k-slice [64w, 64w+64) = 4 k16-steps
    uint32_t asum[4][4];
    {
        const int k0w = warp*64;
#pragma unroll
        for (int ks = 0; ks < 4; ++ks) {
            const int kk = k0w + ks*16 + 2*tig;
            asum[ks][0] = pbf(summ[g*D_ + kk],         summ[g*D_ + kk + 1]);
            asum[ks][1] = pbf(summ[(g+8)*D_ + kk],     summ[(g+8)*D_ + kk + 1]);
            asum[ks][2] = pbf(summ[g*D_ + kk + 8],     summ[g*D_ + kk + 9]);
            asum[ks][3] = pbf(summ[(g+8)*D_ + kk + 8], summ[(g+8)*D_ + kk + 9]);
        }
    }

    float gacc[8][4];
#pragma unroll
    for (int nt = 0; nt < 8; ++nt) { gacc[nt][0]=0.f; gacc[nt][1]=0.f; gacc[nt][2]=0.f; gacc[nt][3]=0.f; }
    float colacc[8];
#pragma unroll
    for (int nt = 0; nt < 8; ++nt) colacc[nt] = 0.f;
    float zacc = 0.f;
    const int lo = t >> 3, jp = t & 7;         // exp thread mapping (t < 128)
    uint32_t* esb = (uint32_t*)&sA[OFF_EB];

    STAGE(0, 0);

    for (int it = 0; it < NT; ++it) {
        if (it + 1 < NT) {
            STAGE(it + 1, (it + 1) & 1);
            asm volatile("cp.async.wait_group 1;\n" ::: "memory");
        } else {
            asm volatile("cp.async.wait_group 0;\n" ::: "memory");
        }
        __syncthreads();

        const float* tile = sA + (it & 1)*BUF;

        // ---- P1 scores: 4 x k16 per warp, rows 0-7 (s0) and 8-15 (s1) ----
        {
            float s0[4] = {0.f,0.f,0.f,0.f}, s1[4] = {0.f,0.f,0.f,0.f};
            const int k0w = warp*64;
#pragma unroll
            for (int ks = 0; ks < 4; ++ks) {
                const int kk = k0w + ks*16 + 2*tig;
                uint32_t b0[2], b1[2];
                {   float2 p = *(const float2*)&tile[g*TP + kk];
                    float2 q = *(const float2*)&tile[g*TP + kk + 8];
                    b0[0] = pbf(p.x, p.y); b0[1] = pbf(q.x, q.y); }
                {   float2 p = *(const float2*)&tile[(8+g)*TP + kk];
                    float2 q = *(const float2*)&tile[(8+g)*TP + kk + 8];
                    b1[0] = pbf(p.x, p.y); b1[1] = pbf(q.x, q.y); }
                mma_bf16(s0, asum[ks], b0);
                mma_bf16(s1, asum[ks], b1);
            }
            float* red = sA + OFF_RD + warp*(L_*RP);
            *(float2*)&red[g*RP     + 2*tig]     = make_float2(s0[0], s0[1]);
            *(float2*)&red[(g+8)*RP + 2*tig]     = make_float2(s0[2], s0[3]);
            *(float2*)&red[g*RP     + 8 + 2*tig] = make_float2(s1[0], s1[1]);
            *(float2*)&red[(g+8)*RP + 8 + 2*tig] = make_float2(s1[2], s1[3]);
        }
        __syncthreads();

        // ---- P2 exp: 128 threads, each a (l, j-pair); pack bf16x2 ----
        if (t < 128) {
            float v0 = 0.f, v1 = 0.f;
#pragma unroll
            for (int w = 0; w < 16; ++w) {
                float2 p = *(const float2*)&sA[OFF_RD + w*(L_*RP) + lo*RP + 2*jp];
                v0 += p.x; v1 += p.y;
            }
            float e0 = __expf(v0 * 0.03125f) - 1.0f;   // scores O(0.05): no max sub
            float e1 = __expf(v1 * 0.03125f) - 1.0f;
            esb[lo*EPB + jp] = pbf(e0, e1);
            zacc += e0 + e1;
        }
        __syncthreads();

        // ---- P3 ctx: warp d-slice [64w, +64); single k16 MMA per 8-col nt ----
        {
            uint32_t ae[4];
            ae[0] = esb[g*EPB + tig];
            ae[1] = esb[(g+8)*EPB + tig];
            ae[2] = esb[g*EPB + tig + 4];
            ae[3] = esb[(g+8)*EPB + tig + 4];
#pragma unroll
            for (int nt = 0; nt < 8; ++nt) {
                const int c = warp*64 + nt*8 + g;
                float f0 = tile[(2*tig)*TP     + c];
                float f1 = tile[(2*tig+1)*TP   + c];
                float f2 = tile[(2*tig+8)*TP   + c];
                float f3 = tile[(2*tig+9)*TP   + c];
                colacc[nt] += (f0 + f1) + (f2 + f3);
                uint32_t bfr[2];
                bfr[0] = pbf(f0, f1);
                bfr[1] = pbf(f2, f3);
                mma_bf16(gacc[nt], ae, bfr);
            }
        }
        __syncthreads();
    }
#undef STAGE

    // ---- epilogue ----
#pragma unroll
    for (int nt = 0; nt < 8; ++nt) {
        float v = colacc[nt];
        v += __shfl_xor_sync(0xFFFFFFFFu, v, 1);
        v += __shfl_xor_sync(0xFFFFFFFFu, v, 2);
        if (tig == 0) g_cs[bx*D_ + warp*64 + nt*8 + g] = v;
    }

    if (t < 128) sA[OFF_ZB + lo*RP + jp] = zacc;
    __syncthreads();
    if (t < L_) {
        float z = 0.f;
#pragma unroll
        for (int j = 0; j < 8; ++j) z += sA[OFF_ZB + t*RP + j];
        g_z[bx*L_ + t] = z;                    // sum(e-1); +S added in kF
    }

#pragma unroll
    for (int nt = 0; nt < 8; ++nt) {
        const int d0 = warp*64 + nt*8 + 2*tig;
        *(float2*)&g_G[((size_t)bx*L_ + g    )*D_ + d0] = make_float2(gacc[nt][0], gacc[nt][1]);
        *(float2*)&g_G[((size_t)bx*L_ + g + 8)*D_ + d0] = make_float2(gacc[nt][2], gacc[nt][3]);
    }
}

// ---------------------------------------------------------------------------
// Reduce: out[b,d] = C0*colsum + sum_l c_bl*G
// ---------------------------------------------------------------------------
__global__ void __launch_bounds__(256, 2)
kF(const float* __restrict__ wproj, float* __restrict__ out) {
    const int t  = threadIdx.x;
    const int bx = blockIdx.x;
    const int b  = bx >> 6;
    const int dc = bx & 63;
    const int dd = t & 15;
    const int jg = t >> 4;
    const int d  = dc*16 + dd;

    __shared__ float cl[L_];
    __shared__ float C0s;
    __shared__ float sred[16][17];

    if (t < L_) {
        float Z = (float)S_;
#pragma unroll
        for (int j = 0; j < CTAB; ++j) Z += g_z[(b*CTAB + j)*L_ + t];
        cl[t] = wproj[t] / Z;
    }
    __syncthreads();
    if (t == 0) {
        float c0 = 0.f;
#pragma unroll
        for (int l = 0; l < L_; ++l) c0 += cl[l];
        C0s = c0;
    }
    __syncthreads();

    float pacc = C0s * g_cs[(b*CTAB + jg)*D_ + d];
    const float* Gp = &g_G[((size_t)(b*CTAB + jg))*L_*D_ + d];
#pragma unroll
    for (int l = 0; l < L_; ++l) pacc += cl[l] * Gp[(size_t)l*D_];
    sred[jg][dd] = pacc;
    __syncthreads();
    if (t < 16) {
        float r = 0.f;
#pragma unroll
        for (int jj = 0; jj < 16; ++jj) r += sred[jj][t];
        out[b*D_ + dc*16 + t] = r;
    }
}

// Diagnostic no-ops: make the launch period 7 so the profiled launch
// (global index 7 -> 7 mod 7 = 0) is kMain. Removed next round.
__global__ void kDummy() {}

// ---------------------------------------------------------------------------
extern "C" void kernel_launch(void* const* d_in, const int* in_sizes, int n_in,
                              void* d_out, int out_size) {
    const float* mem = nullptr;
    const float* summ = nullptr;
    const float* w = nullptr;
    for (int i = 0; i < n_in; ++i) {
        if      (in_sizes[i] == B_*S_*D_) mem  = (const float*)d_in[i];
        else if (in_sizes[i] == L_*D_)    summ = (const float*)d_in[i];
        else if (in_sizes[i] == L_)       w    = (const float*)d_in[i];
    }
    static bool attrDone = false;
    if (!attrDone) {
        cudaFuncSetAttribute(kMain, cudaFuncAttributeMaxDynamicSharedMemorySize, SMEM_BYTES);
        attrDone = true;
    }
    kMain<<<GRID, THR, SMEM_BYTES>>>(mem, summ);
    kF<<<512, 256>>>(w, (float*)d_out);
    kDummy<<<1, 32>>>();
    kDummy<<<1, 32>>>();
    kDummy<<<1, 32>>>();
    kDummy<<<1, 32>>>();
    kDummy<<<1, 32>>>();
}